// round 14
// baseline (speedup 1.0000x reference)
#include <cuda_runtime.h>
#include <cuda_fp16.h>
#include <stdint.h>

// ---------------- problem constants ----------------
#define SEQ   512
#define BATCH 64
#define DIN   1024
#define DH    1024
#define NG    4096            // 4 gates * DH, reordered r = j*4 + g
#define MTOT  (SEQ * BATCH)

// ---------------- device scratch ----------------
__device__ __align__(16) __half g_Wxf[(size_t)NG * 1024];    // 8.4 MB fp16
__device__ __align__(16) __half g_Whf[(size_t)NG * 1024];    // 8.4 MB fp16
__device__ __align__(16) __half g_Xsf[(size_t)MTOT * 1024];  // 64 MB  x fp16
__device__ __align__(16) __half g_hs[2][BATCH * 1024];       // h fp16 ping-pong
__device__ float g_bias[NG];
__device__ float g_pre[(size_t)SEQ * NG * BATCH];            // 512 MB pre[t][r][b]
__device__ int   g_sync[2];                                  // per-group step barrier

// ---------------- asm helpers (baseline PTX only) ----------------
__device__ __forceinline__ uint32_t smem_u32(const void* p) {
    uint32_t a;
    asm("{ .reg .u64 t; cvta.to.shared.u64 t, %1; cvt.u32.u64 %0, t; }" : "=r"(a) : "l"(p));
    return a;
}
#define CP16(dst, src) asm volatile("cp.async.cg.shared.global [%0], [%1], 16;" :: "r"(dst), "l"(src))
#define CP_COMMIT()    asm volatile("cp.async.commit_group;" ::: "memory")
#define CP_WAIT(n)     asm volatile("cp.async.wait_group %0;" :: "n"(n) : "memory")

#define LDSM4(r0, r1, r2, r3, a) \
    asm volatile("ldmatrix.sync.aligned.m8n8.x4.shared.b16 {%0,%1,%2,%3}, [%4];" \
                 : "=r"(r0), "=r"(r1), "=r"(r2), "=r"(r3) : "r"(a))

#define MMAH(d, a0, a1, a2, a3, b0, b1) \
    asm volatile("mma.sync.aligned.m16n8k16.row.col.f32.f16.f16.f32 " \
                 "{%0,%1,%2,%3}, {%4,%5,%6,%7}, {%8,%9}, {%0,%1,%2,%3};" \
                 : "+f"((d)[0]), "+f"((d)[1]), "+f"((d)[2]), "+f"((d)[3]) \
                 : "r"(a0), "r"(a1), "r"(a2), "r"(a3), "r"(b0), "r"(b1))

__device__ __forceinline__ float sigf(float x) { return 1.0f / (1.0f + __expf(-x)); }
__device__ __forceinline__ float tanhfast(float x) { return 1.0f - 2.0f / (__expf(2.0f * x) + 1.0f); }

// ---------------- prep: weights + X -> fp16, bias, zero states ----------------
__global__ void prep_kernel(const float* __restrict__ X,
                            const float* __restrict__ Wf, const float* __restrict__ bf,
                            const float* __restrict__ Wi, const float* __restrict__ bi,
                            const float* __restrict__ Wg, const float* __restrict__ bg,
                            const float* __restrict__ Wo, const float* __restrict__ bo) {
    int idx = blockIdx.x * blockDim.x + threadIdx.x;
    int stride = gridDim.x * blockDim.x;
    if (idx == 0) { g_sync[0] = 0; g_sync[1] = 0; }
    for (int i = idx; i < NG * 512; i += stride) {
        int r = i >> 9;
        int k4 = (i & 511) * 4;
        int j = r >> 2, g = r & 3;
        const float* W = (g == 0) ? Wf : (g == 1) ? Wi : (g == 2) ? Wg : Wo;
        float4 v = *(const float4*)(W + (size_t)j * 2048 + k4);
        union { __half h[4]; uint2 u; } h4;
        h4.h[0] = __float2half(v.x); h4.h[1] = __float2half(v.y);
        h4.h[2] = __float2half(v.z); h4.h[3] = __float2half(v.w);
        if (k4 < 1024) *(uint2*)(g_Wxf + (size_t)r * 1024 + k4)          = h4.u;
        else           *(uint2*)(g_Whf + (size_t)r * 1024 + (k4 - 1024)) = h4.u;
    }
    for (int i = idx; i < MTOT * 256; i += stride) {
        float4 v = *(const float4*)(X + (size_t)i * 4);
        union { __half h[4]; uint2 u; } h4;
        h4.h[0] = __float2half(v.x); h4.h[1] = __float2half(v.y);
        h4.h[2] = __float2half(v.z); h4.h[3] = __float2half(v.w);
        *(uint2*)(g_Xsf + (size_t)i * 4) = h4.u;
    }
    for (int i = idx; i < NG; i += stride) {
        int j = i >> 2, g = i & 3;
        const float* b = (g == 0) ? bf : (g == 1) ? bi : (g == 2) ? bg : bo;
        g_bias[i] = b[j];
    }
    for (int i = idx; i < BATCH * 1024; i += stride) {
        g_hs[0][i] = __float2half(0.0f);
        g_hs[1][i] = __float2half(0.0f);
    }
}

// ============================================================
// xproj (unchanged, verified R10): pre[t][r][b] = Wxf . x^T + bias
// ============================================================
#define XP_STAGE 18432
#define XP_SMEM  (3 * XP_STAGE * 2)

__global__ __launch_bounds__(256, 1) void xproj_kernel() {
    extern __shared__ __half smem[];
    const uint32_t sb = smem_u32(smem);
    const int tid  = threadIdx.x;
    const int lane = tid & 31;
    const int wid  = tid >> 5;
    const int wm   = wid & 3;
    const int wn   = wid >> 2;
    const int r0   = blockIdx.x * 128;
    const int tok0 = blockIdx.y * 128;

    const int lrow = tid >> 3;
    const int lseg = (tid & 7) * 8;

    const uint32_t aBase = sb + ((wm * 32 + (lane & 15)) * 72 + ((lane >> 4) * 8)) * 2;
    const uint32_t bBase = sb + (9216 + (wn * 64 + (lane & 15)) * 72 + ((lane >> 4) * 8)) * 2;

    float acc[2][8][4];
#pragma unroll
    for (int i = 0; i < 2; i++)
#pragma unroll
        for (int n = 0; n < 8; n++)
#pragma unroll
            for (int q = 0; q < 4; q++) acc[i][n][q] = 0.0f;

    const int NC = 16;
#pragma unroll
    for (int s = 0; s < 2; s++) {
        const int kb = s * 64;
#pragma unroll
        for (int j = 0; j < 4; j++) {
            int row = lrow + j * 32;
            CP16(sb + (s * XP_STAGE + row * 72 + lseg) * 2,
                 g_Wxf + (size_t)(r0 + row) * 1024 + kb + lseg);
            CP16(sb + (s * XP_STAGE + 9216 + row * 72 + lseg) * 2,
                 g_Xsf + (size_t)(tok0 + row) * 1024 + kb + lseg);
        }
        CP_COMMIT();
    }

    for (int c = 0; c < NC; c++) {
        CP_WAIT(1);
        __syncthreads();
        if (c + 2 < NC) {
            const int s = (c + 2) % 3;
            const int kb = (c + 2) * 64;
#pragma unroll
            for (int j = 0; j < 4; j++) {
                int row = lrow + j * 32;
                CP16(sb + (s * XP_STAGE + row * 72 + lseg) * 2,
                     g_Wxf + (size_t)(r0 + row) * 1024 + kb + lseg);
                CP16(sb + (s * XP_STAGE + 9216 + row * 72 + lseg) * 2,
                     g_Xsf + (size_t)(tok0 + row) * 1024 + kb + lseg);
            }
        }
        CP_COMMIT();

        const uint32_t stOff = (uint32_t)((c % 3) * XP_STAGE) * 2;
#pragma unroll
        for (int s4 = 0; s4 < 4; s4++) {
            const uint32_t kOff = s4 * 32;
            uint32_t a0, a1, a2, a3, a4, a5, a6, a7;
            LDSM4(a0, a1, a2, a3, aBase + stOff + kOff);
            LDSM4(a4, a5, a6, a7, aBase + stOff + kOff + 16 * 144);
#pragma unroll
            for (int g = 0; g < 4; g++) {
                uint32_t b0, b1, b2, b3;
                LDSM4(b0, b1, b2, b3, bBase + stOff + kOff + g * 16 * 144);
                MMAH(acc[0][2 * g],     a0, a1, a2, a3, b0, b2);
                MMAH(acc[0][2 * g + 1], a0, a1, a2, a3, b1, b3);
                MMAH(acc[1][2 * g],     a4, a5, a6, a7, b0, b2);
                MMAH(acc[1][2 * g + 1], a4, a5, a6, a7, b1, b3);
            }
        }
    }
    CP_WAIT(0);

    const int gq = lane >> 2;
    const int t4 = lane & 3;
#pragma unroll
    for (int mi = 0; mi < 2; mi++) {
        const int R = r0 + wm * 32 + mi * 16 + gq;
        const float bias0 = g_bias[R];
        const float bias8 = g_bias[R + 8];
#pragma unroll
        for (int nb = 0; nb < 8; nb++) {
            const int n = wn * 64 + nb * 8 + t4 * 2;
            const int token = tok0 + n;
            const int tt = token >> 6;
            const int bb = token & 63;
            float* p0 = g_pre + ((size_t)tt * NG + R) * 64 + bb;
            *(float2*)p0 = make_float2(acc[mi][nb][0] + bias0, acc[mi][nb][1] + bias0);
            *(float2*)(p0 + 8 * 64) = make_float2(acc[mi][nb][2] + bias8, acc[mi][nb][3] + bias8);
        }
    }
}

// ============================================================
// persistent recurrence, batch-split: 128 CTAs = 2 groups x 64 CTAs.
// CTA: M=64 gate rows, N=32 batch, K=1024.
// 8 warps: wm=wid&3 (m16), wn=wid>>2 (n16). A panel 64x1024 resident.
// B = h_sub (32x1024) in 2 chunks of 512, both issued at step start
// (2-stage, one CP_WAIT+sync per chunk). Chunk = 2048 CP16 -> 8/thread.
// ============================================================
#define PS_A_STRIDE 1032
#define PS_A_BYTES  (64 * PS_A_STRIDE * 2)            // 132096
#define PS_B_STRIDE 520
#define PS_B_STAGE  (32 * PS_B_STRIDE * 2)            // 33280
#define PS_B_OFF    PS_A_BYTES
#define PS_ZB_OFF   (PS_A_BYTES + 2 * PS_B_STAGE)     // 198656
#define PS_SMEM     (PS_ZB_OFF + 64 * 34 * 4)         // 207360

__global__ __launch_bounds__(256, 1) void persistent_kernel(float* __restrict__ out) {
    extern __shared__ __half smem[];
    const uint32_t sb = smem_u32(smem);
    const int tid  = threadIdx.x;
    const int lane = tid & 31;
    const int wid  = tid >> 5;
    const int wm   = wid & 3;               // m block of 16 (0..3)
    const int wn   = wid >> 2;              // n block of 16 (0..1)
    const int grp  = blockIdx.x >> 6;       // 0,1
    const int gid  = blockIdx.x & 63;       // CTA within group
    const int r0   = gid * 64;
    const int bOff = grp * 32;              // batch offset

    // ---- A panel resident: 64 rows x 1024 fp16 (8192 uint4, 32/thread) ----
    for (int i = tid; i < 64 * 128; i += 256) {
        int row = i >> 7;
        int seg = (i & 127) * 8;
        uint4 v = *(const uint4*)(g_Whf + (size_t)(r0 + row) * 1024 + seg);
        *(uint4*)((char*)smem + (row * PS_A_STRIDE + seg) * 2) = v;
    }
    __syncthreads();

    const uint32_t aBase = sb + ((wm * 16 + (lane & 15)) * PS_A_STRIDE + (lane >> 4) * 8) * 2;
    const uint32_t bBase = sb + PS_B_OFF + ((wn * 16 + (lane & 15)) * PS_B_STRIDE + (lane >> 4) * 8) * 2;
    float* zbuf = (float*)((char*)smem + PS_ZB_OFF);

    const int gq  = lane >> 2;
    const int t4  = lane & 3;
    const int R1  = wm * 16 + gq;           // 0..63 local gate row (with +8)
    const int lb  = tid >> 3;               // 0..31 local batch (gate pass)
    const int jp  = tid & 7;                // jl = jp*2 + q
    float creg[2] = {0.0f, 0.0f};

    for (int t = 0; t < SEQ; t++) {
        const __half* hsrc = g_hs[t & 1] + (size_t)bOff * 1024;
        const float* pre_t = g_pre + (size_t)t * NG * 64;

        // issue both 512-wide chunks immediately (separate commit groups)
        // chunk = 32 rows x 64 uint4 = 2048 CP16 -> 8 per thread
#pragma unroll
        for (int s = 0; s < 2; s++) {
#pragma unroll
            for (int i = 0; i < 8; i++) {
                int idx = tid + i * 256;                 // 0..2047
                int row = idx >> 6;                      // 0..31
                int seg = (idx & 63) * 8;                // 0..504
                CP16(sb + PS_B_OFF + s * PS_B_STAGE + (row * PS_B_STRIDE + seg) * 2,
                     hsrc + (size_t)row * 1024 + s * 512 + seg);
            }
            CP_COMMIT();
        }

        // prefetch pre tile: 2 n-blocks x rows (R1, R1+8), 2 cols each
        float2 pf[2][2];
#pragma unroll
        for (int nb = 0; nb < 2; nb++) {
            const int col = bOff + wn * 16 + nb * 8 + t4 * 2;   // global batch col
            pf[nb][0] = *(const float2*)(pre_t + (size_t)(r0 + R1) * 64 + col);
            pf[nb][1] = *(const float2*)(pre_t + (size_t)(r0 + R1 + 8) * 64 + col);
        }

        float acc[2][4];
#pragma unroll
        for (int n = 0; n < 2; n++)
#pragma unroll
            for (int q = 0; q < 4; q++) acc[n][q] = 0.0f;

#pragma unroll
        for (int kc = 0; kc < 2; kc++) {
            if (kc == 0) CP_WAIT(1); else CP_WAIT(0);
            __syncthreads();
            const uint32_t stB = (uint32_t)(kc * PS_B_STAGE);
            const uint32_t kA  = (uint32_t)(kc * 1024);          // 512 elems * 2 bytes
#pragma unroll
            for (int s4 = 0; s4 < 32; s4++) {
                uint32_t a0, a1, a2, a3;
                LDSM4(a0, a1, a2, a3, aBase + kA + s4 * 32);
                uint32_t b0, b1, b2, b3;
                LDSM4(b0, b1, b2, b3, bBase + stB + s4 * 32);
                MMAH(acc[0], a0, a1, a2, a3, b0, b2);
                MMAH(acc[1], a0, a1, a2, a3, b1, b3);
            }
        }

        // ---- z = acc + pre -> zbuf (local batch cols, stride 34) ----
#pragma unroll
        for (int nb = 0; nb < 2; nb++) {
            const int zc = wn * 16 + nb * 8 + t4 * 2;           // local col 0..31
            zbuf[R1 * 34 + zc]           = acc[nb][0] + pf[nb][0].x;
            zbuf[R1 * 34 + zc + 1]       = acc[nb][1] + pf[nb][0].y;
            zbuf[(R1 + 8) * 34 + zc]     = acc[nb][2] + pf[nb][1].x;
            zbuf[(R1 + 8) * 34 + zc + 1] = acc[nb][3] + pf[nb][1].y;
        }
        __syncthreads();

        // ---- gate pass: 2 cells per thread (consecutive j), c in registers ----
        const int b    = bOff + lb;                   // global batch
        const int jbase = gid * 16 + jp * 2;          // global hidden idx base
        float hval[2];
        union { __half h[2]; uint32_t u; } hh;
#pragma unroll
        for (int q = 0; q < 2; q++) {
            const int jl = jp * 2 + q;                // 0..15
            float zf = zbuf[(jl * 4 + 0) * 34 + lb];
            float zi = zbuf[(jl * 4 + 1) * 34 + lb];
            float zg = zbuf[(jl * 4 + 2) * 34 + lb];
            float zo = zbuf[(jl * 4 + 3) * 34 + lb];
            float f  = sigf(zf);
            float ig = sigf(zi);
            float gg = tanhfast(zg);
            float oo = sigf(zo);
            creg[q] = f * creg[q] + ig * gg;
            float h = oo * tanhfast(creg[q]);
            hval[q] = h;
            hh.h[q] = __float2half(h);
        }
        *(uint32_t*)(g_hs[(t + 1) & 1] + (size_t)b * 1024 + jbase) = hh.u;

        // ---- release: sync, then tid0-only fence + arrive on group barrier ----
        __syncthreads();
        if (tid == 0) { __threadfence(); atomicAdd(&g_sync[grp], 1); }

        // off-critical-path output stores
        *(float2*)(out + (size_t)t * BATCH * DH + (size_t)b * DH + jbase) =
            make_float2(hval[0], hval[1]);
        if (t == SEQ - 1) {
            const size_t outs = (size_t)SEQ * BATCH * DH;
            *(float2*)(out + outs + (size_t)b * DH + jbase) = make_float2(hval[0], hval[1]);
            *(float2*)(out + outs + BATCH * DH + (size_t)b * DH + jbase) =
                make_float2(creg[0], creg[1]);
        }

        if (tid == 0) {
            const int target = 64 * (t + 1);
            while (*(volatile int*)&g_sync[grp] < target) {}
            __threadfence();
        }
        __syncthreads();
    }
}

// ---------------- launch ----------------
extern "C" void kernel_launch(void* const* d_in, const int* in_sizes, int n_in,
                              void* d_out, int out_size) {
    const float* X  = (const float*)d_in[0];
    const float* Wf = (const float*)d_in[1];
    const float* bf = (const float*)d_in[2];
    const float* Wi = (const float*)d_in[3];
    const float* bi = (const float*)d_in[4];
    const float* Wg = (const float*)d_in[5];
    const float* bg = (const float*)d_in[6];
    const float* Wo = (const float*)d_in[7];
    const float* bo = (const float*)d_in[8];
    float* out = (float*)d_out;

    static int attr_done = 0;
    if (!attr_done) {
        cudaFuncSetAttribute(xproj_kernel, cudaFuncAttributeMaxDynamicSharedMemorySize, XP_SMEM);
        cudaFuncSetAttribute(persistent_kernel, cudaFuncAttributeMaxDynamicSharedMemorySize, PS_SMEM);
        attr_done = 1;
    }

    prep_kernel<<<4096, 256>>>(X, Wf, bf, Wi, bi, Wg, bg, Wo, bo);

    dim3 gx(32, 256);
    xproj_kernel<<<gx, 256, XP_SMEM>>>();

    persistent_kernel<<<128, 256, PS_SMEM>>>(out);
}

// round 15
// speedup vs baseline: 1.0047x; 1.0047x over previous
#include <cuda_runtime.h>
#include <cuda_fp16.h>
#include <stdint.h>

// ---------------- problem constants ----------------
#define SEQ   512
#define BATCH 64
#define DIN   1024
#define DH    1024
#define NG    4096            // 4 gates * DH, reordered r = j*4 + g
#define MTOT  (SEQ * BATCH)

// ---------------- device scratch ----------------
__device__ __align__(16) __half g_Wxf[(size_t)NG * 1024];    // 8.4 MB fp16
__device__ __align__(16) __half g_Whf[(size_t)NG * 1024];    // 8.4 MB fp16
__device__ __align__(16) __half g_Xsf[(size_t)MTOT * 1024];  // 64 MB  x fp16
__device__ __align__(16) __half g_hs[2][BATCH * 1024];       // h fp16 ping-pong
__device__ float g_bias[NG];
__device__ float g_pre[(size_t)SEQ * NG * BATCH];            // 512 MB pre[t][r][b]
__device__ int   g_flags[2][64 * 32];                        // per-CTA step flags, 128B stride

// ---------------- asm helpers (baseline PTX only) ----------------
__device__ __forceinline__ uint32_t smem_u32(const void* p) {
    uint32_t a;
    asm("{ .reg .u64 t; cvta.to.shared.u64 t, %1; cvt.u32.u64 %0, t; }" : "=r"(a) : "l"(p));
    return a;
}
#define CP16(dst, src) asm volatile("cp.async.cg.shared.global [%0], [%1], 16;" :: "r"(dst), "l"(src))
#define CP_COMMIT()    asm volatile("cp.async.commit_group;" ::: "memory")
#define CP_WAIT(n)     asm volatile("cp.async.wait_group %0;" :: "n"(n) : "memory")

#define LDSM4(r0, r1, r2, r3, a) \
    asm volatile("ldmatrix.sync.aligned.m8n8.x4.shared.b16 {%0,%1,%2,%3}, [%4];" \
                 : "=r"(r0), "=r"(r1), "=r"(r2), "=r"(r3) : "r"(a))

#define MMAH(d, a0, a1, a2, a3, b0, b1) \
    asm volatile("mma.sync.aligned.m16n8k16.row.col.f32.f16.f16.f32 " \
                 "{%0,%1,%2,%3}, {%4,%5,%6,%7}, {%8,%9}, {%0,%1,%2,%3};" \
                 : "+f"((d)[0]), "+f"((d)[1]), "+f"((d)[2]), "+f"((d)[3]) \
                 : "r"(a0), "r"(a1), "r"(a2), "r"(a3), "r"(b0), "r"(b1))

__device__ __forceinline__ float sigf(float x) { return 1.0f / (1.0f + __expf(-x)); }
__device__ __forceinline__ float tanhfast(float x) { return 1.0f - 2.0f / (__expf(2.0f * x) + 1.0f); }

// ---------------- prep: weights + X -> fp16, bias, zero states ----------------
__global__ void prep_kernel(const float* __restrict__ X,
                            const float* __restrict__ Wf, const float* __restrict__ bf,
                            const float* __restrict__ Wi, const float* __restrict__ bi,
                            const float* __restrict__ Wg, const float* __restrict__ bg,
                            const float* __restrict__ Wo, const float* __restrict__ bo) {
    int idx = blockIdx.x * blockDim.x + threadIdx.x;
    int stride = gridDim.x * blockDim.x;
    for (int i = idx; i < 2 * 64 * 32; i += stride) ((int*)g_flags)[i] = 0;
    for (int i = idx; i < NG * 512; i += stride) {
        int r = i >> 9;
        int k4 = (i & 511) * 4;
        int j = r >> 2, g = r & 3;
        const float* W = (g == 0) ? Wf : (g == 1) ? Wi : (g == 2) ? Wg : Wo;
        float4 v = *(const float4*)(W + (size_t)j * 2048 + k4);
        union { __half h[4]; uint2 u; } h4;
        h4.h[0] = __float2half(v.x); h4.h[1] = __float2half(v.y);
        h4.h[2] = __float2half(v.z); h4.h[3] = __float2half(v.w);
        if (k4 < 1024) *(uint2*)(g_Wxf + (size_t)r * 1024 + k4)          = h4.u;
        else           *(uint2*)(g_Whf + (size_t)r * 1024 + (k4 - 1024)) = h4.u;
    }
    for (int i = idx; i < MTOT * 256; i += stride) {
        float4 v = *(const float4*)(X + (size_t)i * 4);
        union { __half h[4]; uint2 u; } h4;
        h4.h[0] = __float2half(v.x); h4.h[1] = __float2half(v.y);
        h4.h[2] = __float2half(v.z); h4.h[3] = __float2half(v.w);
        *(uint2*)(g_Xsf + (size_t)i * 4) = h4.u;
    }
    for (int i = idx; i < NG; i += stride) {
        int j = i >> 2, g = i & 3;
        const float* b = (g == 0) ? bf : (g == 1) ? bi : (g == 2) ? bg : bo;
        g_bias[i] = b[j];
    }
    for (int i = idx; i < BATCH * 1024; i += stride) {
        g_hs[0][i] = __float2half(0.0f);
        g_hs[1][i] = __float2half(0.0f);
    }
}

// ============================================================
// xproj (unchanged, verified R10): pre[t][r][b] = Wxf . x^T + bias
// ============================================================
#define XP_STAGE 18432
#define XP_SMEM  (3 * XP_STAGE * 2)

__global__ __launch_bounds__(256, 1) void xproj_kernel() {
    extern __shared__ __half smem[];
    const uint32_t sb = smem_u32(smem);
    const int tid  = threadIdx.x;
    const int lane = tid & 31;
    const int wid  = tid >> 5;
    const int wm   = wid & 3;
    const int wn   = wid >> 2;
    const int r0   = blockIdx.x * 128;
    const int tok0 = blockIdx.y * 128;

    const int lrow = tid >> 3;
    const int lseg = (tid & 7) * 8;

    const uint32_t aBase = sb + ((wm * 32 + (lane & 15)) * 72 + ((lane >> 4) * 8)) * 2;
    const uint32_t bBase = sb + (9216 + (wn * 64 + (lane & 15)) * 72 + ((lane >> 4) * 8)) * 2;

    float acc[2][8][4];
#pragma unroll
    for (int i = 0; i < 2; i++)
#pragma unroll
        for (int n = 0; n < 8; n++)
#pragma unroll
            for (int q = 0; q < 4; q++) acc[i][n][q] = 0.0f;

    const int NC = 16;
#pragma unroll
    for (int s = 0; s < 2; s++) {
        const int kb = s * 64;
#pragma unroll
        for (int j = 0; j < 4; j++) {
            int row = lrow + j * 32;
            CP16(sb + (s * XP_STAGE + row * 72 + lseg) * 2,
                 g_Wxf + (size_t)(r0 + row) * 1024 + kb + lseg);
            CP16(sb + (s * XP_STAGE + 9216 + row * 72 + lseg) * 2,
                 g_Xsf + (size_t)(tok0 + row) * 1024 + kb + lseg);
        }
        CP_COMMIT();
    }

    for (int c = 0; c < NC; c++) {
        CP_WAIT(1);
        __syncthreads();
        if (c + 2 < NC) {
            const int s = (c + 2) % 3;
            const int kb = (c + 2) * 64;
#pragma unroll
            for (int j = 0; j < 4; j++) {
                int row = lrow + j * 32;
                CP16(sb + (s * XP_STAGE + row * 72 + lseg) * 2,
                     g_Wxf + (size_t)(r0 + row) * 1024 + kb + lseg);
                CP16(sb + (s * XP_STAGE + 9216 + row * 72 + lseg) * 2,
                     g_Xsf + (size_t)(tok0 + row) * 1024 + kb + lseg);
            }
        }
        CP_COMMIT();

        const uint32_t stOff = (uint32_t)((c % 3) * XP_STAGE) * 2;
#pragma unroll
        for (int s4 = 0; s4 < 4; s4++) {
            const uint32_t kOff = s4 * 32;
            uint32_t a0, a1, a2, a3, a4, a5, a6, a7;
            LDSM4(a0, a1, a2, a3, aBase + stOff + kOff);
            LDSM4(a4, a5, a6, a7, aBase + stOff + kOff + 16 * 144);
#pragma unroll
            for (int g = 0; g < 4; g++) {
                uint32_t b0, b1, b2, b3;
                LDSM4(b0, b1, b2, b3, bBase + stOff + kOff + g * 16 * 144);
                MMAH(acc[0][2 * g],     a0, a1, a2, a3, b0, b2);
                MMAH(acc[0][2 * g + 1], a0, a1, a2, a3, b1, b3);
                MMAH(acc[1][2 * g],     a4, a5, a6, a7, b0, b2);
                MMAH(acc[1][2 * g + 1], a4, a5, a6, a7, b1, b3);
            }
        }
    }
    CP_WAIT(0);

    const int gq = lane >> 2;
    const int t4 = lane & 3;
#pragma unroll
    for (int mi = 0; mi < 2; mi++) {
        const int R = r0 + wm * 32 + mi * 16 + gq;
        const float bias0 = g_bias[R];
        const float bias8 = g_bias[R + 8];
#pragma unroll
        for (int nb = 0; nb < 8; nb++) {
            const int n = wn * 64 + nb * 8 + t4 * 2;
            const int token = tok0 + n;
            const int tt = token >> 6;
            const int bb = token & 63;
            float* p0 = g_pre + ((size_t)tt * NG + R) * 64 + bb;
            *(float2*)p0 = make_float2(acc[mi][nb][0] + bias0, acc[mi][nb][1] + bias0);
            *(float2*)(p0 + 8 * 64) = make_float2(acc[mi][nb][2] + bias8, acc[mi][nb][3] + bias8);
        }
    }
}

// ============================================================
// persistent recurrence, batch-split: 128 CTAs = 2 groups x 64 CTAs.
// CTA: M=64 gate rows, N=32 batch, K=1024.
// A panel 64x1024 resident. B = h_sub (32x1024): 4 chunks of 256, 4 stages,
// ALL issued at step start. Flag-array group barrier (no atomics).
// ============================================================
#define PS_A_STRIDE 1032
#define PS_A_BYTES  (64 * PS_A_STRIDE * 2)            // 132096
#define PS_B_STRIDE 264
#define PS_B_STAGE  (32 * PS_B_STRIDE * 2)            // 16896
#define PS_B_OFF    PS_A_BYTES
#define PS_ZB_OFF   (PS_A_BYTES + 4 * PS_B_STAGE)     // 199680
#define PS_SMEM     (PS_ZB_OFF + 64 * 34 * 4)         // 208384

__global__ __launch_bounds__(256, 1) void persistent_kernel(float* __restrict__ out) {
    extern __shared__ __half smem[];
    const uint32_t sb = smem_u32(smem);
    const int tid  = threadIdx.x;
    const int lane = tid & 31;
    const int wid  = tid >> 5;
    const int wm   = wid & 3;               // m block of 16 (0..3)
    const int wn   = wid >> 2;              // n block of 16 (0..1)
    const int grp  = blockIdx.x >> 6;       // 0,1
    const int gid  = blockIdx.x & 63;       // CTA within group
    const int r0   = gid * 64;
    const int bOff = grp * 32;              // batch offset

    // ---- A panel resident: 64 rows x 1024 fp16 (8192 uint4, 32/thread) ----
    for (int i = tid; i < 64 * 128; i += 256) {
        int row = i >> 7;
        int seg = (i & 127) * 8;
        uint4 v = *(const uint4*)(g_Whf + (size_t)(r0 + row) * 1024 + seg);
        *(uint4*)((char*)smem + (row * PS_A_STRIDE + seg) * 2) = v;
    }
    __syncthreads();

    const uint32_t aBase = sb + ((wm * 16 + (lane & 15)) * PS_A_STRIDE + (lane >> 4) * 8) * 2;
    const uint32_t bBase = sb + PS_B_OFF + ((wn * 16 + (lane & 15)) * PS_B_STRIDE + (lane >> 4) * 8) * 2;
    float* zbuf = (float*)((char*)smem + PS_ZB_OFF);
    volatile int* myflag = &g_flags[grp][gid * 32];

    const int gq  = lane >> 2;
    const int t4  = lane & 3;
    const int R1  = wm * 16 + gq;           // local gate row (with +8)
    const int lb  = tid >> 3;               // 0..31 local batch (gate pass)
    const int jp  = tid & 7;                // jl = jp*2 + q
    float creg[2] = {0.0f, 0.0f};

    // prefetch pre for t=0
    float2 pf[2][2];
    {
        const float* pre_t = g_pre;
#pragma unroll
        for (int nb = 0; nb < 2; nb++) {
            const int col = bOff + wn * 16 + nb * 8 + t4 * 2;
            pf[nb][0] = *(const float2*)(pre_t + (size_t)(r0 + R1) * 64 + col);
            pf[nb][1] = *(const float2*)(pre_t + (size_t)(r0 + R1 + 8) * 64 + col);
        }
    }

    for (int t = 0; t < SEQ; t++) {
        const __half* hsrc = g_hs[t & 1] + (size_t)bOff * 1024;

        // ---- issue ALL 4 B chunks (256 k each) into 4 stages ----
#pragma unroll
        for (int s = 0; s < 4; s++) {
#pragma unroll
            for (int i = 0; i < 4; i++) {
                int idx = tid + i * 256;                 // 0..1023
                int row = idx >> 5;                      // 0..31
                int seg = (idx & 31) * 8;
                CP16(sb + PS_B_OFF + s * PS_B_STAGE + (row * PS_B_STRIDE + seg) * 2,
                     hsrc + (size_t)row * 1024 + s * 256 + seg);
            }
            CP_COMMIT();
        }

        float acc[2][4];
#pragma unroll
        for (int n = 0; n < 2; n++)
#pragma unroll
            for (int q = 0; q < 4; q++) acc[n][q] = 0.0f;

#pragma unroll
        for (int kc = 0; kc < 4; kc++) {
            if      (kc == 0) CP_WAIT(3);
            else if (kc == 1) CP_WAIT(2);
            else if (kc == 2) CP_WAIT(1);
            else              CP_WAIT(0);
            __syncthreads();
            const uint32_t stB = (uint32_t)(kc * PS_B_STAGE);
            const uint32_t kA  = (uint32_t)(kc * 512);          // 256 elems * 2 bytes
#pragma unroll
            for (int s4 = 0; s4 < 16; s4++) {
                uint32_t a0, a1, a2, a3;
                LDSM4(a0, a1, a2, a3, aBase + kA + s4 * 32);
                uint32_t b0, b1, b2, b3;
                LDSM4(b0, b1, b2, b3, bBase + stB + s4 * 32);
                MMAH(acc[0], a0, a1, a2, a3, b0, b2);
                MMAH(acc[1], a0, a1, a2, a3, b1, b3);
            }
        }

        // ---- z = acc + pre -> zbuf (local batch cols, stride 34) ----
#pragma unroll
        for (int nb = 0; nb < 2; nb++) {
            const int zc = wn * 16 + nb * 8 + t4 * 2;           // local col 0..31
            zbuf[R1 * 34 + zc]           = acc[nb][0] + pf[nb][0].x;
            zbuf[R1 * 34 + zc + 1]       = acc[nb][1] + pf[nb][0].y;
            zbuf[(R1 + 8) * 34 + zc]     = acc[nb][2] + pf[nb][1].x;
            zbuf[(R1 + 8) * 34 + zc + 1] = acc[nb][3] + pf[nb][1].y;
        }
        __syncthreads();

        // ---- gate pass: 2 cells per thread (consecutive j), c in registers ----
        const int b    = bOff + lb;                   // global batch
        const int jbase = gid * 16 + jp * 2;          // global hidden idx base
        float hval[2];
        union { __half h[2]; uint32_t u; } hh;
#pragma unroll
        for (int q = 0; q < 2; q++) {
            const int jl = jp * 2 + q;                // 0..15
            float zf = zbuf[(jl * 4 + 0) * 34 + lb];
            float zi = zbuf[(jl * 4 + 1) * 34 + lb];
            float zg = zbuf[(jl * 4 + 2) * 34 + lb];
            float zo = zbuf[(jl * 4 + 3) * 34 + lb];
            float f  = sigf(zf);
            float ig = sigf(zi);
            float gg = tanhfast(zg);
            float oo = sigf(zo);
            creg[q] = f * creg[q] + ig * gg;
            float h = oo * tanhfast(creg[q]);
            hval[q] = h;
            hh.h[q] = __float2half(h);
        }
        *(uint32_t*)(g_hs[(t + 1) & 1] + (size_t)b * 1024 + jbase) = hh.u;

        // ---- release: sync, then tid0 fence + flag store ----
        __syncthreads();
        if (tid == 0) { __threadfence(); *myflag = t + 1; }

        // off-critical-path output stores + pre prefetch for t+1 (overlap spin)
        *(float2*)(out + (size_t)t * BATCH * DH + (size_t)b * DH + jbase) =
            make_float2(hval[0], hval[1]);
        if (t == SEQ - 1) {
            const size_t outs = (size_t)SEQ * BATCH * DH;
            *(float2*)(out + outs + (size_t)b * DH + jbase) = make_float2(hval[0], hval[1]);
            *(float2*)(out + outs + BATCH * DH + (size_t)b * DH + jbase) =
                make_float2(creg[0], creg[1]);
        } else {
            const float* pre_n = g_pre + (size_t)(t + 1) * NG * 64;
#pragma unroll
            for (int nb = 0; nb < 2; nb++) {
                const int col = bOff + wn * 16 + nb * 8 + t4 * 2;
                pf[nb][0] = *(const float2*)(pre_n + (size_t)(r0 + R1) * 64 + col);
                pf[nb][1] = *(const float2*)(pre_n + (size_t)(r0 + R1 + 8) * 64 + col);
            }
        }

        // ---- wait: 64 threads poll one flag each, then fence + join ----
        if (tid < 64) {
            volatile int* f = &g_flags[grp][tid * 32];
            while (*f < t + 1) {}
            __threadfence();
        }
        __syncthreads();
    }
}

// ---------------- launch ----------------
extern "C" void kernel_launch(void* const* d_in, const int* in_sizes, int n_in,
                              void* d_out, int out_size) {
    const float* X  = (const float*)d_in[0];
    const float* Wf = (const float*)d_in[1];
    const float* bf = (const float*)d_in[2];
    const float* Wi = (const float*)d_in[3];
    const float* bi = (const float*)d_in[4];
    const float* Wg = (const float*)d_in[5];
    const float* bg = (const float*)d_in[6];
    const float* Wo = (const float*)d_in[7];
    const float* bo = (const float*)d_in[8];
    float* out = (float*)d_out;

    static int attr_done = 0;
    if (!attr_done) {
        cudaFuncSetAttribute(xproj_kernel, cudaFuncAttributeMaxDynamicSharedMemorySize, XP_SMEM);
        cudaFuncSetAttribute(persistent_kernel, cudaFuncAttributeMaxDynamicSharedMemorySize, PS_SMEM);
        attr_done = 1;
    }

    prep_kernel<<<4096, 256>>>(X, Wf, bf, Wi, bi, Wg, bg, Wo, bo);

    dim3 gx(32, 256);
    xproj_kernel<<<gx, 256, XP_SMEM>>>();

    persistent_kernel<<<128, 256, PS_SMEM>>>(out);
}

// round 16
// speedup vs baseline: 1.0304x; 1.0255x over previous
#include <cuda_runtime.h>
#include <cuda_fp16.h>
#include <stdint.h>

// ---------------- problem constants ----------------
#define SEQ   512
#define BATCH 64
#define DIN   1024
#define DH    1024
#define NG    4096            // 4 gates * DH, reordered r = j*4 + g
#define MTOT  (SEQ * BATCH)

// ---------------- device scratch ----------------
__device__ __align__(16) __half g_Wxf[(size_t)NG * 1024];    // 8.4 MB fp16
__device__ __align__(16) __half g_Whf[(size_t)NG * 1024];    // 8.4 MB fp16
__device__ __align__(16) __half g_Xsf[(size_t)MTOT * 1024];  // 64 MB  x fp16
__device__ __align__(16) __half g_hs[2][BATCH * 1024];       // h fp16 ping-pong
__device__ float g_bias[NG];
__device__ float g_pre[(size_t)SEQ * NG * BATCH];            // 512 MB pre[t][r][b]
__device__ int   g_sync[2];                                  // per-group step barrier

// ---------------- asm helpers (baseline PTX only) ----------------
__device__ __forceinline__ uint32_t smem_u32(const void* p) {
    uint32_t a;
    asm("{ .reg .u64 t; cvta.to.shared.u64 t, %1; cvt.u32.u64 %0, t; }" : "=r"(a) : "l"(p));
    return a;
}
#define CP16(dst, src) asm volatile("cp.async.cg.shared.global [%0], [%1], 16;" :: "r"(dst), "l"(src))
#define CP_COMMIT()    asm volatile("cp.async.commit_group;" ::: "memory")
#define CP_WAIT(n)     asm volatile("cp.async.wait_group %0;" :: "n"(n) : "memory")

#define LDSM4(r0, r1, r2, r3, a) \
    asm volatile("ldmatrix.sync.aligned.m8n8.x4.shared.b16 {%0,%1,%2,%3}, [%4];" \
                 : "=r"(r0), "=r"(r1), "=r"(r2), "=r"(r3) : "r"(a))

#define MMAH(d, a0, a1, a2, a3, b0, b1) \
    asm volatile("mma.sync.aligned.m16n8k16.row.col.f32.f16.f16.f32 " \
                 "{%0,%1,%2,%3}, {%4,%5,%6,%7}, {%8,%9}, {%0,%1,%2,%3};" \
                 : "+f"((d)[0]), "+f"((d)[1]), "+f"((d)[2]), "+f"((d)[3]) \
                 : "r"(a0), "r"(a1), "r"(a2), "r"(a3), "r"(b0), "r"(b1))

__device__ __forceinline__ float sigf(float x) { return 1.0f / (1.0f + __expf(-x)); }
__device__ __forceinline__ float tanhfast(float x) { return 1.0f - 2.0f / (__expf(2.0f * x) + 1.0f); }

// ---------------- prep: weights + X -> fp16, bias, zero states ----------------
__global__ void prep_kernel(const float* __restrict__ X,
                            const float* __restrict__ Wf, const float* __restrict__ bf,
                            const float* __restrict__ Wi, const float* __restrict__ bi,
                            const float* __restrict__ Wg, const float* __restrict__ bg,
                            const float* __restrict__ Wo, const float* __restrict__ bo) {
    int idx = blockIdx.x * blockDim.x + threadIdx.x;
    int stride = gridDim.x * blockDim.x;
    if (idx == 0) { g_sync[0] = 0; g_sync[1] = 0; }
    for (int i = idx; i < NG * 512; i += stride) {
        int r = i >> 9;
        int k4 = (i & 511) * 4;
        int j = r >> 2, g = r & 3;
        const float* W = (g == 0) ? Wf : (g == 1) ? Wi : (g == 2) ? Wg : Wo;
        float4 v = *(const float4*)(W + (size_t)j * 2048 + k4);
        union { __half h[4]; uint2 u; } h4;
        h4.h[0] = __float2half(v.x); h4.h[1] = __float2half(v.y);
        h4.h[2] = __float2half(v.z); h4.h[3] = __float2half(v.w);
        if (k4 < 1024) *(uint2*)(g_Wxf + (size_t)r * 1024 + k4)          = h4.u;
        else           *(uint2*)(g_Whf + (size_t)r * 1024 + (k4 - 1024)) = h4.u;
    }
    for (int i = idx; i < MTOT * 256; i += stride) {
        float4 v = *(const float4*)(X + (size_t)i * 4);
        union { __half h[4]; uint2 u; } h4;
        h4.h[0] = __float2half(v.x); h4.h[1] = __float2half(v.y);
        h4.h[2] = __float2half(v.z); h4.h[3] = __float2half(v.w);
        *(uint2*)(g_Xsf + (size_t)i * 4) = h4.u;
    }
    for (int i = idx; i < NG; i += stride) {
        int j = i >> 2, g = i & 3;
        const float* b = (g == 0) ? bf : (g == 1) ? bi : (g == 2) ? bg : bo;
        g_bias[i] = b[j];
    }
    for (int i = idx; i < BATCH * 1024; i += stride) {
        g_hs[0][i] = __float2half(0.0f);
        g_hs[1][i] = __float2half(0.0f);
    }
}

// ============================================================
// xproj (unchanged, verified R10): pre[t][r][b] = Wxf . x^T + bias
// ============================================================
#define XP_STAGE 18432
#define XP_SMEM  (3 * XP_STAGE * 2)

__global__ __launch_bounds__(256, 1) void xproj_kernel() {
    extern __shared__ __half smem[];
    const uint32_t sb = smem_u32(smem);
    const int tid  = threadIdx.x;
    const int lane = tid & 31;
    const int wid  = tid >> 5;
    const int wm   = wid & 3;
    const int wn   = wid >> 2;
    const int r0   = blockIdx.x * 128;
    const int tok0 = blockIdx.y * 128;

    const int lrow = tid >> 3;
    const int lseg = (tid & 7) * 8;

    const uint32_t aBase = sb + ((wm * 32 + (lane & 15)) * 72 + ((lane >> 4) * 8)) * 2;
    const uint32_t bBase = sb + (9216 + (wn * 64 + (lane & 15)) * 72 + ((lane >> 4) * 8)) * 2;

    float acc[2][8][4];
#pragma unroll
    for (int i = 0; i < 2; i++)
#pragma unroll
        for (int n = 0; n < 8; n++)
#pragma unroll
            for (int q = 0; q < 4; q++) acc[i][n][q] = 0.0f;

    const int NC = 16;
#pragma unroll
    for (int s = 0; s < 2; s++) {
        const int kb = s * 64;
#pragma unroll
        for (int j = 0; j < 4; j++) {
            int row = lrow + j * 32;
            CP16(sb + (s * XP_STAGE + row * 72 + lseg) * 2,
                 g_Wxf + (size_t)(r0 + row) * 1024 + kb + lseg);
            CP16(sb + (s * XP_STAGE + 9216 + row * 72 + lseg) * 2,
                 g_Xsf + (size_t)(tok0 + row) * 1024 + kb + lseg);
        }
        CP_COMMIT();
    }

    for (int c = 0; c < NC; c++) {
        CP_WAIT(1);
        __syncthreads();
        if (c + 2 < NC) {
            const int s = (c + 2) % 3;
            const int kb = (c + 2) * 64;
#pragma unroll
            for (int j = 0; j < 4; j++) {
                int row = lrow + j * 32;
                CP16(sb + (s * XP_STAGE + row * 72 + lseg) * 2,
                     g_Wxf + (size_t)(r0 + row) * 1024 + kb + lseg);
                CP16(sb + (s * XP_STAGE + 9216 + row * 72 + lseg) * 2,
                     g_Xsf + (size_t)(tok0 + row) * 1024 + kb + lseg);
            }
        }
        CP_COMMIT();

        const uint32_t stOff = (uint32_t)((c % 3) * XP_STAGE) * 2;
#pragma unroll
        for (int s4 = 0; s4 < 4; s4++) {
            const uint32_t kOff = s4 * 32;
            uint32_t a0, a1, a2, a3, a4, a5, a6, a7;
            LDSM4(a0, a1, a2, a3, aBase + stOff + kOff);
            LDSM4(a4, a5, a6, a7, aBase + stOff + kOff + 16 * 144);
#pragma unroll
            for (int g = 0; g < 4; g++) {
                uint32_t b0, b1, b2, b3;
                LDSM4(b0, b1, b2, b3, bBase + stOff + kOff + g * 16 * 144);
                MMAH(acc[0][2 * g],     a0, a1, a2, a3, b0, b2);
                MMAH(acc[0][2 * g + 1], a0, a1, a2, a3, b1, b3);
                MMAH(acc[1][2 * g],     a4, a5, a6, a7, b0, b2);
                MMAH(acc[1][2 * g + 1], a4, a5, a6, a7, b1, b3);
            }
        }
    }
    CP_WAIT(0);

    const int gq = lane >> 2;
    const int t4 = lane & 3;
#pragma unroll
    for (int mi = 0; mi < 2; mi++) {
        const int R = r0 + wm * 32 + mi * 16 + gq;
        const float bias0 = g_bias[R];
        const float bias8 = g_bias[R + 8];
#pragma unroll
        for (int nb = 0; nb < 8; nb++) {
            const int n = wn * 64 + nb * 8 + t4 * 2;
            const int token = tok0 + n;
            const int tt = token >> 6;
            const int bb = token & 63;
            float* p0 = g_pre + ((size_t)tt * NG + R) * 64 + bb;
            *(float2*)p0 = make_float2(acc[mi][nb][0] + bias0, acc[mi][nb][1] + bias0);
            *(float2*)(p0 + 8 * 64) = make_float2(acc[mi][nb][2] + bias8, acc[mi][nb][3] + bias8);
        }
    }
}

// ============================================================
// persistent recurrence, batch-split: 128 CTAs = 2 groups x 64 CTAs.
// CTA: M=64 gate rows, N=32 batch, K=1024.  (R13 base + pre prefetch in spin)
// A panel 64x1024 resident. B = h_sub (32x1024) in 4 chunks of 256, 3-stage.
// ============================================================
#define PS_A_STRIDE 1032
#define PS_A_BYTES  (64 * PS_A_STRIDE * 2)            // 132096
#define PS_B_STRIDE 264
#define PS_B_STAGE  (32 * PS_B_STRIDE * 2)            // 16896
#define PS_B_OFF    PS_A_BYTES
#define PS_ZB_OFF   (PS_A_BYTES + 3 * PS_B_STAGE)     // 182784
#define PS_SMEM     (PS_ZB_OFF + 64 * 34 * 4)         // 191488

__global__ __launch_bounds__(256, 1) void persistent_kernel(float* __restrict__ out) {
    extern __shared__ __half smem[];
    const uint32_t sb = smem_u32(smem);
    const int tid  = threadIdx.x;
    const int lane = tid & 31;
    const int wid  = tid >> 5;
    const int wm   = wid & 3;               // m block of 16 (0..3)
    const int wn   = wid >> 2;              // n block of 16 (0..1)
    const int grp  = blockIdx.x >> 6;       // 0,1
    const int gid  = blockIdx.x & 63;       // CTA within group
    const int r0   = gid * 64;
    const int bOff = grp * 32;              // batch offset

    // ---- A panel resident: 64 rows x 1024 fp16 (8192 uint4, 32/thread) ----
    for (int i = tid; i < 64 * 128; i += 256) {
        int row = i >> 7;
        int seg = (i & 127) * 8;
        uint4 v = *(const uint4*)(g_Whf + (size_t)(r0 + row) * 1024 + seg);
        *(uint4*)((char*)smem + (row * PS_A_STRIDE + seg) * 2) = v;
    }
    __syncthreads();

    const uint32_t aBase = sb + ((wm * 16 + (lane & 15)) * PS_A_STRIDE + (lane >> 4) * 8) * 2;
    const uint32_t bBase = sb + PS_B_OFF + ((wn * 16 + (lane & 15)) * PS_B_STRIDE + (lane >> 4) * 8) * 2;
    float* zbuf = (float*)((char*)smem + PS_ZB_OFF);

    const int gq  = lane >> 2;
    const int t4  = lane & 3;
    const int R1  = wm * 16 + gq;           // local gate row (with +8)
    const int lb  = tid >> 3;               // 0..31 local batch (gate pass)
    const int jp  = tid & 7;                // jl = jp*2 + q
    float creg[2] = {0.0f, 0.0f};

    // prefetch pre for t=0
    float2 pf[2][2];
    {
        const float* pre_t = g_pre;
#pragma unroll
        for (int nb = 0; nb < 2; nb++) {
            const int col = bOff + wn * 16 + nb * 8 + t4 * 2;
            pf[nb][0] = *(const float2*)(pre_t + (size_t)(r0 + R1) * 64 + col);
            pf[nb][1] = *(const float2*)(pre_t + (size_t)(r0 + R1 + 8) * 64 + col);
        }
    }

    for (int t = 0; t < SEQ; t++) {
        const __half* hsrc = g_hs[t & 1] + (size_t)bOff * 1024;

        // prologue: chunks 0,1 (1024 CP16 per chunk -> 4/thread)
#pragma unroll
        for (int s = 0; s < 2; s++) {
#pragma unroll
            for (int i = 0; i < 4; i++) {
                int idx = tid + i * 256;                 // 0..1023
                int row = idx >> 5;                      // 0..31
                int seg = (idx & 31) * 8;
                CP16(sb + PS_B_OFF + s * PS_B_STAGE + (row * PS_B_STRIDE + seg) * 2,
                     hsrc + (size_t)row * 1024 + s * 256 + seg);
            }
            CP_COMMIT();
        }

        float acc[2][4];
#pragma unroll
        for (int n = 0; n < 2; n++)
#pragma unroll
            for (int q = 0; q < 4; q++) acc[n][q] = 0.0f;

#pragma unroll
        for (int kc = 0; kc < 4; kc++) {
            CP_WAIT(1);
            __syncthreads();
            if (kc + 2 < 4) {
                const int s = (kc + 2) % 3;
#pragma unroll
                for (int i = 0; i < 4; i++) {
                    int idx = tid + i * 256;
                    int row = idx >> 5;
                    int seg = (idx & 31) * 8;
                    CP16(sb + PS_B_OFF + s * PS_B_STAGE + (row * PS_B_STRIDE + seg) * 2,
                         hsrc + (size_t)row * 1024 + (kc + 2) * 256 + seg);
                }
            }
            CP_COMMIT();

            const uint32_t stB = (uint32_t)((kc % 3) * PS_B_STAGE);
            const uint32_t kA  = (uint32_t)(kc * 512);          // 256 elems * 2 bytes
#pragma unroll
            for (int s4 = 0; s4 < 16; s4++) {
                uint32_t a0, a1, a2, a3;
                LDSM4(a0, a1, a2, a3, aBase + kA + s4 * 32);
                uint32_t b0, b1, b2, b3;
                LDSM4(b0, b1, b2, b3, bBase + stB + s4 * 32);
                MMAH(acc[0], a0, a1, a2, a3, b0, b2);
                MMAH(acc[1], a0, a1, a2, a3, b1, b3);
            }
        }

        // ---- z = acc + pre -> zbuf (local batch cols, stride 34) ----
#pragma unroll
        for (int nb = 0; nb < 2; nb++) {
            const int zc = wn * 16 + nb * 8 + t4 * 2;           // local col 0..31
            zbuf[R1 * 34 + zc]           = acc[nb][0] + pf[nb][0].x;
            zbuf[R1 * 34 + zc + 1]       = acc[nb][1] + pf[nb][0].y;
            zbuf[(R1 + 8) * 34 + zc]     = acc[nb][2] + pf[nb][1].x;
            zbuf[(R1 + 8) * 34 + zc + 1] = acc[nb][3] + pf[nb][1].y;
        }
        __syncthreads();

        // ---- gate pass: 2 cells per thread (consecutive j), c in registers ----
        const int b    = bOff + lb;                   // global batch
        const int jbase = gid * 16 + jp * 2;          // global hidden idx base
        float hval[2];
        union { __half h[2]; uint32_t u; } hh;
#pragma unroll
        for (int q = 0; q < 2; q++) {
            const int jl = jp * 2 + q;                // 0..15
            float zf = zbuf[(jl * 4 + 0) * 34 + lb];
            float zi = zbuf[(jl * 4 + 1) * 34 + lb];
            float zg = zbuf[(jl * 4 + 2) * 34 + lb];
            float zo = zbuf[(jl * 4 + 3) * 34 + lb];
            float f  = sigf(zf);
            float ig = sigf(zi);
            float gg = tanhfast(zg);
            float oo = sigf(zo);
            creg[q] = f * creg[q] + ig * gg;
            float h = oo * tanhfast(creg[q]);
            hval[q] = h;
            hh.h[q] = __float2half(h);
        }
        *(uint32_t*)(g_hs[(t + 1) & 1] + (size_t)b * 1024 + jbase) = hh.u;

        // ---- release: sync, then tid0-only fence + arrive on group barrier ----
        __syncthreads();
        if (tid == 0) { __threadfence(); atomicAdd(&g_sync[grp], 1); }

        // off-critical-path output stores + pre[t+1] prefetch (hidden in spin)
        *(float2*)(out + (size_t)t * BATCH * DH + (size_t)b * DH + jbase) =
            make_float2(hval[0], hval[1]);
        if (t == SEQ - 1) {
            const size_t outs = (size_t)SEQ * BATCH * DH;
            *(float2*)(out + outs + (size_t)b * DH + jbase) = make_float2(hval[0], hval[1]);
            *(float2*)(out + outs + BATCH * DH + (size_t)b * DH + jbase) =
                make_float2(creg[0], creg[1]);
        } else {
            const float* pre_n = g_pre + (size_t)(t + 1) * NG * 64;
#pragma unroll
            for (int nb = 0; nb < 2; nb++) {
                const int col = bOff + wn * 16 + nb * 8 + t4 * 2;
                pf[nb][0] = *(const float2*)(pre_n + (size_t)(r0 + R1) * 64 + col);
                pf[nb][1] = *(const float2*)(pre_n + (size_t)(r0 + R1 + 8) * 64 + col);
            }
        }

        if (tid == 0) {
            const int target = 64 * (t + 1);
            while (*(volatile int*)&g_sync[grp] < target) {}
            __threadfence();
        }
        __syncthreads();
    }
}

// ---------------- launch ----------------
extern "C" void kernel_launch(void* const* d_in, const int* in_sizes, int n_in,
                              void* d_out, int out_size) {
    const float* X  = (const float*)d_in[0];
    const float* Wf = (const float*)d_in[1];
    const float* bf = (const float*)d_in[2];
    const float* Wi = (const float*)d_in[3];
    const float* bi = (const float*)d_in[4];
    const float* Wg = (const float*)d_in[5];
    const float* bg = (const float*)d_in[6];
    const float* Wo = (const float*)d_in[7];
    const float* bo = (const float*)d_in[8];
    float* out = (float*)d_out;

    static int attr_done = 0;
    if (!attr_done) {
        cudaFuncSetAttribute(xproj_kernel, cudaFuncAttributeMaxDynamicSharedMemorySize, XP_SMEM);
        cudaFuncSetAttribute(persistent_kernel, cudaFuncAttributeMaxDynamicSharedMemorySize, PS_SMEM);
        attr_done = 1;
    }

    prep_kernel<<<4096, 256>>>(X, Wf, bf, Wi, bi, Wg, bg, Wo, bo);

    dim3 gx(32, 256);
    xproj_kernel<<<gx, 256, XP_SMEM>>>();

    persistent_kernel<<<128, 256, PS_SMEM>>>(out);
}